// round 3
// baseline (speedup 1.0000x reference)
#include <cuda_runtime.h>
#include <cuda_bf16.h>
#include <math.h>

#define NN 100000
#define EE 1600000
#define FIN 128
#define HID 32
#define HEADS 8
#define D1 256        // HEADS*HID
#define NCLS 40
#define BETA 0.1f
#define ONE_MB 0.9f   // 1-beta
#define LRA 0.2f      // leaky relu alpha

// ------------- scratch (device globals; total ~162 MB, < 256 MB) -------------
__device__ __align__(128) float g_H0[(size_t)NN * D1];   // x@Wcat; becomes layer-1 out in place
__device__ __align__(128) float g_FA[(size_t)NN * HID];  // per-head hop-1 result
__device__ __align__(128) float g_O0[(size_t)NN * NCLS]; // H @ W_out
__device__ __align__(128) float g_GA[(size_t)NN * NCLS]; // layer-2 hop-1 result
__device__ __align__(128) float g_W1[EE];                // attention weights (CSR order)
__device__ __align__(128) int   g_SSRC[EE];              // src sorted by dst (CSR)
__device__ int   g_ROWPTR[NN + 1];
__device__ int   g_DEG[NN];
__device__ int   g_CUR[NN];
__device__ float g_S[NN];
__device__ float g_T[NN];
__device__ int   g_EI64;    // 1 if edge_index is int64, 0 if int32

// ------------------------------- helpers --------------------------------------
__device__ __forceinline__ float warp_sum(float v) {
#pragma unroll
    for (int o = 16; o > 0; o >>= 1) v += __shfl_xor_sync(0xffffffffu, v, o);
    return v;
}
__device__ __forceinline__ float warp_max(float v) {
#pragma unroll
    for (int o = 16; o > 0; o >>= 1) v = fmaxf(v, __shfl_xor_sync(0xffffffffu, v, o));
    return v;
}

// ------------------------- edge dtype sniff -----------------------------------
// int64 values < 2^31, little-endian: odd 32-bit words are all 0.
// int32: odd words are random node ids (512 consecutive zeros is impossible
// for this input distribution).
__global__ void sniff_kernel(const int* __restrict__ ei32) {
    if (threadIdx.x == 0 && blockIdx.x == 0) {
        int is64 = 1;
        for (int i = 0; i < 512; i++) {
            if (ei32[2 * i + 1] != 0) { is64 = 0; break; }
        }
        g_EI64 = is64;
    }
}

__device__ __forceinline__ int load_node(const void* ei, size_t pos, int is64) {
    if (is64) return (int)((const long long*)ei)[pos];
    return ((const int*)ei)[pos];
}

// ------------------------------ CSR build -------------------------------------
__global__ void zero_counts_kernel() {
    int i = blockIdx.x * blockDim.x + threadIdx.x;
    if (i < NN) { g_DEG[i] = 0; g_CUR[i] = 0; }
}

__global__ void build_deg_kernel(const void* __restrict__ ei) {
    int e = blockIdx.x * blockDim.x + threadIdx.x;
    if (e >= EE) return;
    int is64 = g_EI64;
    int d = load_node(ei, (size_t)EE + e, is64);
    if ((unsigned)d < NN) atomicAdd(&g_DEG[d], 1);
}

// single-block exclusive scan of DEG -> ROWPTR
__global__ void scan_kernel() {
    __shared__ int wsum[32];
    int tid = threadIdx.x, lane = tid & 31, wid = tid >> 5;
    int offset = 0;
    if (tid == 0) g_ROWPTR[0] = 0;
    for (int base = 0; base < NN; base += 4096) {
        int i0 = base + tid * 4;
        int a0 = (i0 + 0 < NN) ? g_DEG[i0 + 0] : 0;
        int a1 = (i0 + 1 < NN) ? g_DEG[i0 + 1] : 0;
        int a2 = (i0 + 2 < NN) ? g_DEG[i0 + 2] : 0;
        int a3 = (i0 + 3 < NN) ? g_DEG[i0 + 3] : 0;
        int tsum = a0 + a1 + a2 + a3;
        int x = tsum;
#pragma unroll
        for (int o = 1; o < 32; o <<= 1) {
            int y = __shfl_up_sync(0xffffffffu, x, o);
            if (lane >= o) x += y;
        }
        if (lane == 31) wsum[wid] = x;
        __syncthreads();
        if (wid == 0) {
            int w = wsum[lane];
#pragma unroll
            for (int o = 1; o < 32; o <<= 1) {
                int y = __shfl_up_sync(0xffffffffu, w, o);
                if (lane >= o) w += y;
            }
            wsum[lane] = w;
        }
        __syncthreads();
        int woff = (wid == 0) ? 0 : wsum[wid - 1];
        int excl = offset + woff + (x - tsum);
        if (i0 + 0 < NN) g_ROWPTR[i0 + 1] = excl + a0;
        if (i0 + 1 < NN) g_ROWPTR[i0 + 2] = excl + a0 + a1;
        if (i0 + 2 < NN) g_ROWPTR[i0 + 3] = excl + a0 + a1 + a2;
        if (i0 + 3 < NN) g_ROWPTR[i0 + 4] = excl + tsum;
        int btot = wsum[31];
        __syncthreads();
        offset += btot;
    }
}

__global__ void scatter_kernel(const void* __restrict__ ei) {
    int e = blockIdx.x * blockDim.x + threadIdx.x;
    if (e >= EE) return;
    int is64 = g_EI64;
    int s = load_node(ei, (size_t)e, is64);
    int d = load_node(ei, (size_t)EE + e, is64);
    if ((unsigned)d >= NN || (unsigned)s >= NN) return;
    int pos = g_ROWPTR[d] + atomicAdd(&g_CUR[d], 1);
    if ((unsigned)pos < EE) g_SSRC[pos] = s;
}

// --------------------------------- GEMM1 --------------------------------------
// H0[n, h*32+j] = sum_k x[n,k] * W[h,k,j].   64x64 tiles, 4x4 per thread.
__global__ void gemm1_kernel(const float* __restrict__ x, const float* __restrict__ W) {
    __shared__ float As[64][65];
    __shared__ float Bs[64][65];
    int tx = threadIdx.x & 15, ty = threadIdx.x >> 4;
    int rowBase = blockIdx.x * 64;
    int colBase = blockIdx.y * 64;
    float acc[4][4] = {};
    for (int kt = 0; kt < FIN; kt += 64) {
#pragma unroll
        for (int i = 0; i < 16; i++) {
            int idx = threadIdx.x + i * 256;
            int r = idx >> 6, c = idx & 63;
            int gr = rowBase + r;
            As[r][c] = (gr < NN) ? x[(size_t)gr * FIN + kt + c] : 0.0f;
        }
#pragma unroll
        for (int i = 0; i < 16; i++) {
            int idx = threadIdx.x + i * 256;
            int r = idx >> 6, c = idx & 63;
            int col = colBase + c;
            Bs[r][c] = W[(size_t)(col >> 5) * (FIN * HID) + (size_t)(kt + r) * HID + (col & 31)];
        }
        __syncthreads();
#pragma unroll 16
        for (int k = 0; k < 64; k++) {
            float a0 = As[ty * 4 + 0][k];
            float a1 = As[ty * 4 + 1][k];
            float a2 = As[ty * 4 + 2][k];
            float a3 = As[ty * 4 + 3][k];
            float b0 = Bs[k][tx * 4 + 0];
            float b1 = Bs[k][tx * 4 + 1];
            float b2 = Bs[k][tx * 4 + 2];
            float b3 = Bs[k][tx * 4 + 3];
            acc[0][0] += a0 * b0; acc[0][1] += a0 * b1; acc[0][2] += a0 * b2; acc[0][3] += a0 * b3;
            acc[1][0] += a1 * b0; acc[1][1] += a1 * b1; acc[1][2] += a1 * b2; acc[1][3] += a1 * b3;
            acc[2][0] += a2 * b0; acc[2][1] += a2 * b1; acc[2][2] += a2 * b2; acc[2][3] += a2 * b3;
            acc[3][0] += a3 * b0; acc[3][1] += a3 * b1; acc[3][2] += a3 * b2; acc[3][3] += a3 * b3;
        }
        __syncthreads();
    }
#pragma unroll
    for (int i = 0; i < 4; i++) {
        int gr = rowBase + ty * 4 + i;
        if (gr < NN) {
#pragma unroll
            for (int j = 0; j < 4; j++)
                g_H0[(size_t)gr * D1 + colBase + tx * 4 + j] = acc[i][j];
        }
    }
}

// --------------------------------- GEMM2 --------------------------------------
// O0 = H0[N,256] @ Wout[256,40]. One thread per row; B broadcast from smem.
__global__ void gemm2_kernel(const float* __restrict__ Wout) {
    __shared__ float Bs[D1 * NCLS];
    int tid = threadIdx.x;
    for (int i = tid; i < D1 * NCLS; i += 256) Bs[i] = Wout[i];
    __syncthreads();
    int row = blockIdx.x * 256 + tid;
    if (row >= NN) return;
    const float* arow = g_H0 + (size_t)row * D1;
    float acc[NCLS] = {};
#pragma unroll 4
    for (int k = 0; k < D1; k++) {
        float a = __ldg(arow + k);
        const float* b = &Bs[k * NCLS];
#pragma unroll
        for (int c = 0; c < NCLS; c++) acc[c] += a * b[c];
    }
    float* orow = g_O0 + (size_t)row * NCLS;
#pragma unroll
    for (int c = 0; c < NCLS; c++) orow[c] = acc[c];
}

// ------------------------------ attention s,t ---------------------------------
__global__ void st32_kernel(const float* __restrict__ a_src,
                            const float* __restrict__ a_dst, int h) {
    int gw = blockIdx.x * 8 + (threadIdx.x >> 5);
    int lane = threadIdx.x & 31;
    if (gw >= NN) return;
    float v = g_H0[(size_t)gw * D1 + h * HID + lane];
    float s = v * a_src[h * HID + lane];
    float t = v * a_dst[h * HID + lane];
    s = warp_sum(s);
    t = warp_sum(t);
    if (lane == 0) { g_S[gw] = s; g_T[gw] = t; }
}

__global__ void st40_kernel(const float* __restrict__ a_src,
                            const float* __restrict__ a_dst) {
    int gw = blockIdx.x * 8 + (threadIdx.x >> 5);
    int lane = threadIdx.x & 31;
    if (gw >= NN) return;
    const float* row = g_O0 + (size_t)gw * NCLS;
    float s = row[lane] * a_src[lane];
    float t = row[lane] * a_dst[lane];
    if (lane < 8) {
        s += row[32 + lane] * a_src[32 + lane];
        t += row[32 + lane] * a_dst[32 + lane];
    }
    s = warp_sum(s);
    t = warp_sum(t);
    if (lane == 0) { g_S[gw] = s; g_T[gw] = t; }
}

// -------------------- per-destination softmax over edge segment ---------------
__global__ void attn_w_kernel() {
    int d = blockIdx.x * 8 + (threadIdx.x >> 5);
    int lane = threadIdx.x & 31;
    if (d >= NN) return;
    int start = g_ROWPTR[d], end = g_ROWPTR[d + 1];
    if (start == end) return;
    float td = g_T[d];
    float m = -INFINITY;
    for (int e = start + lane; e < end; e += 32) {
        float ev = g_S[g_SSRC[e]] + td;
        ev = (ev >= 0.0f) ? ev : LRA * ev;
        m = fmaxf(m, ev);
    }
    m = warp_max(m);
    float sum = 0.0f;
    for (int e = start + lane; e < end; e += 32) {
        float ev = g_S[g_SSRC[e]] + td;
        ev = (ev >= 0.0f) ? ev : LRA * ev;
        float p = expf(ev - m);
        g_W1[e] = p;
        sum += p;
    }
    sum = warp_sum(sum);
    float inv = 1.0f / (sum + 1e-16f);
    for (int e = start + lane; e < end; e += 32) g_W1[e] *= inv;
}

// ------------------------------ diffusion hops --------------------------------
// mode 0: msg from H0 head slice -> FA          (feat1 = 0.9*msg + 0.1*h0)
// mode 1: msg from FA -> elu -> H0 head slice   (in place: only element [d,hoff+lane]
//         of H0 is read (teleport) and written; cross-node reads are from FA)
__global__ void hop32_kernel(int h, int mode) {
    int d = blockIdx.x * 8 + (threadIdx.x >> 5);
    int lane = threadIdx.x & 31;
    if (d >= NN) return;
    int hoff = h * HID;
    int start = g_ROWPTR[d], end = g_ROWPTR[d + 1];
    float acc = 0.0f;
    if (mode == 0) {
        for (int e = start; e < end; e++) {
            int s = g_SSRC[e];
            acc += g_W1[e] * g_H0[(size_t)s * D1 + hoff + lane];
        }
    } else {
        for (int e = start; e < end; e++) {
            int s = g_SSRC[e];
            acc += g_W1[e] * g_FA[(size_t)s * HID + lane];
        }
    }
    float h0v = g_H0[(size_t)d * D1 + hoff + lane];
    float v = ONE_MB * acc + BETA * h0v;
    if (mode == 0) {
        g_FA[(size_t)d * HID + lane] = v;
    } else {
        v = (v > 0.0f) ? v : expm1f(v);          // elu
        g_H0[(size_t)d * D1 + hoff + lane] = v;  // in-place layer-1 output
    }
}

// mode 0: msg from O0 -> GA.  mode 1: msg from GA -> elu -> log_softmax -> out.
__global__ void hop40_kernel(int mode, float* __restrict__ out) {
    int d = blockIdx.x * 8 + (threadIdx.x >> 5);
    int lane = threadIdx.x & 31;
    if (d >= NN) return;
    int start = g_ROWPTR[d], end = g_ROWPTR[d + 1];
    float acca = 0.0f, accb = 0.0f;
    bool hi = (lane < 8);
    if (mode == 0) {
        for (int e = start; e < end; e++) {
            int s = g_SSRC[e];
            float w = g_W1[e];
            const float* row = g_O0 + (size_t)s * NCLS;
            acca += w * row[lane];
            if (hi) accb += w * row[32 + lane];
        }
    } else {
        for (int e = start; e < end; e++) {
            int s = g_SSRC[e];
            float w = g_W1[e];
            const float* row = g_GA + (size_t)s * NCLS;
            acca += w * row[lane];
            if (hi) accb += w * row[32 + lane];
        }
    }
    const float* h0row = g_O0 + (size_t)d * NCLS;
    float va = ONE_MB * acca + BETA * h0row[lane];
    float vb = hi ? (ONE_MB * accb + BETA * h0row[32 + lane]) : 0.0f;
    if (mode == 0) {
        float* orow = g_GA + (size_t)d * NCLS;
        orow[lane] = va;
        if (hi) orow[32 + lane] = vb;
    } else {
        float ea = (va > 0.0f) ? va : expm1f(va);
        float eb = hi ? ((vb > 0.0f) ? vb : expm1f(vb)) : -INFINITY;
        float mx = warp_max(fmaxf(ea, eb));
        float se = expf(ea - mx) + (hi ? expf(eb - mx) : 0.0f);
        se = warp_sum(se);
        float lse = mx + logf(se);
        float* orow = out + (size_t)d * NCLS;
        orow[lane] = ea - lse;
        if (hi) orow[32 + lane] = eb - lse;
    }
}

// --------------------------------- launch -------------------------------------
extern "C" void kernel_launch(void* const* d_in, const int* in_sizes, int n_in,
                              void* d_out, int out_size) {
    const float* x     = (const float*)d_in[0];
    const void*  ei    = d_in[1];
    const float* W     = (const float*)d_in[2];
    const float* a_src = (const float*)d_in[3];
    const float* a_dst = (const float*)d_in[4];
    const float* Wout  = (const float*)d_in[5];
    const float* a_so  = (const float*)d_in[6];
    const float* a_do  = (const float*)d_in[7];
    float*       out   = (float*)d_out;

    const int NWARP_GRID = (NN + 7) / 8;       // warp-per-node kernels, 256 thr
    const int EGRID = (EE + 255) / 256;
    const int NGRID = (NN + 255) / 256;

    sniff_kernel<<<1, 32>>>((const int*)ei);
    zero_counts_kernel<<<NGRID, 256>>>();
    build_deg_kernel<<<EGRID, 256>>>(ei);
    scan_kernel<<<1, 1024>>>();
    scatter_kernel<<<EGRID, 256>>>(ei);

    gemm1_kernel<<<dim3((NN + 63) / 64, D1 / 64), 256>>>(x, W);

    for (int h = 0; h < HEADS; h++) {
        st32_kernel<<<NWARP_GRID, 256>>>(a_src, a_dst, h);
        attn_w_kernel<<<NWARP_GRID, 256>>>();
        hop32_kernel<<<NWARP_GRID, 256>>>(h, 0);
        hop32_kernel<<<NWARP_GRID, 256>>>(h, 1);
    }

    gemm2_kernel<<<(NN + 255) / 256, 256>>>(Wout);

    st40_kernel<<<NWARP_GRID, 256>>>(a_so, a_do);
    attn_w_kernel<<<NWARP_GRID, 256>>>();
    hop40_kernel<<<NWARP_GRID, 256>>>(0, nullptr);
    hop40_kernel<<<NWARP_GRID, 256>>>(1, out);
}

// round 5
// speedup vs baseline: 1.2520x; 1.2520x over previous
#include <cuda_runtime.h>
#include <cuda_bf16.h>
#include <math.h>

#define NN 100000
#define EE 1600000
#define FIN 128
#define HID 32
#define HEADS 8
#define D1 256        // HEADS*HID
#define NCLS 40
#define BETA 0.1f
#define ONE_MB 0.9f   // 1-beta
#define LRA 0.2f      // leaky relu alpha
#define SCB 1024
#define NBLK ((NN + SCB - 1) / SCB)

// ------------- scratch (device globals; total ~228 MB, < 256 MB) -------------
__device__ __align__(128) float g_H0[(size_t)NN * D1];    // x@Wcat; layer-1 out in place
__device__ __align__(128) float g_FA[(size_t)NN * 128];   // 4-head-group hop-1 result
__device__ __align__(128) float g_O0[(size_t)NN * NCLS];  // H @ W_out
__device__ __align__(128) float g_GA[(size_t)NN * NCLS];  // layer-2 hop-1 result
__device__ __align__(128) float g_WBUF[(size_t)EE * 4];   // unnorm attn weights (4 heads/edge)
__device__ __align__(128) int   g_SSRC[EE];               // src sorted by dst (CSR)
__device__ __align__(128) float g_S8[(size_t)NN * 8];
__device__ __align__(128) float g_T8[(size_t)NN * 8];
__device__ __align__(128) float g_INV4[(size_t)NN * 4];   // per-dst 1/denom (4 heads)
__device__ int   g_ROWPTR[NN + 1];
__device__ int   g_DEG[NN];
__device__ int   g_CUR[NN];
__device__ int   g_BSUM[NBLK];
__device__ int   g_BOFF[NBLK];
__device__ float g_S[NN];
__device__ float g_T[NN];
__device__ int   g_EI64;    // 1 if edge_index int64, 0 if int32

// ------------------------------- helpers --------------------------------------
__device__ __forceinline__ float warp_sum(float v) {
#pragma unroll
    for (int o = 16; o > 0; o >>= 1) v += __shfl_xor_sync(0xffffffffu, v, o);
    return v;
}
__device__ __forceinline__ float warp_max(float v) {
#pragma unroll
    for (int o = 16; o > 0; o >>= 1) v = fmaxf(v, __shfl_xor_sync(0xffffffffu, v, o));
    return v;
}
__device__ __forceinline__ int warp_sum_i(int v) {
#pragma unroll
    for (int o = 16; o > 0; o >>= 1) v += __shfl_xor_sync(0xffffffffu, v, o);
    return v;
}

// ------------------------- edge dtype sniff (parallel) -------------------------
__global__ void sniff_kernel(const int* __restrict__ ei32) {
    int bad = 0;
    for (int i = threadIdx.x; i < 512; i += 256)
        bad |= (ei32[2 * i + 1] != 0);
    bad = __syncthreads_or(bad);
    if (threadIdx.x == 0) g_EI64 = bad ? 0 : 1;
}

__device__ __forceinline__ int load_node(const void* ei, size_t pos, int is64) {
    if (is64) return (int)((const long long*)ei)[pos];
    return ((const int*)ei)[pos];
}

// ------------------------------ CSR build -------------------------------------
__global__ void zero_counts_kernel() {
    int i = blockIdx.x * blockDim.x + threadIdx.x;
    if (i < NN) { g_DEG[i] = 0; g_CUR[i] = 0; }
}

__global__ void build_deg_kernel(const void* __restrict__ ei) {
    int e = blockIdx.x * blockDim.x + threadIdx.x;
    if (e >= EE) return;
    int d = load_node(ei, (size_t)EE + e, g_EI64);
    if ((unsigned)d < NN) atomicAdd(&g_DEG[d], 1);
}

// two-level scan: A = per-block sums, B = scan of block sums, C = write rowptr
__global__ void scanA_kernel() {
    __shared__ int wsum[8];
    int tid = threadIdx.x;
    int base = blockIdx.x * SCB + tid * 4;
    int s = 0;
#pragma unroll
    for (int j = 0; j < 4; j++) { int i = base + j; if (i < NN) s += g_DEG[i]; }
    s = warp_sum_i(s);
    if ((tid & 31) == 0) wsum[tid >> 5] = s;
    __syncthreads();
    if (tid == 0) {
        int t = 0;
#pragma unroll
        for (int w = 0; w < 8; w++) t += wsum[w];
        g_BSUM[blockIdx.x] = t;
    }
}

__global__ void scanB_kernel() {
    __shared__ int sm[4];
    int tid = threadIdx.x, lane = tid & 31, wid = tid >> 5;
    int v = (tid < NBLK) ? g_BSUM[tid] : 0;
    int x = v;
#pragma unroll
    for (int o = 1; o < 32; o <<= 1) {
        int y = __shfl_up_sync(0xffffffffu, x, o);
        if (lane >= o) x += y;
    }
    if (lane == 31) sm[wid] = x;
    __syncthreads();
    int woff = 0;
    for (int w = 0; w < wid; w++) woff += sm[w];
    if (tid < NBLK) g_BOFF[tid] = woff + x - v;
}

__global__ void scanC_kernel() {
    __shared__ int wsum[8];
    int tid = threadIdx.x, lane = tid & 31, wid = tid >> 5;
    int base = blockIdx.x * SCB + tid * 4;
    int a0 = (base + 0 < NN) ? g_DEG[base + 0] : 0;
    int a1 = (base + 1 < NN) ? g_DEG[base + 1] : 0;
    int a2 = (base + 2 < NN) ? g_DEG[base + 2] : 0;
    int a3 = (base + 3 < NN) ? g_DEG[base + 3] : 0;
    int tsum = a0 + a1 + a2 + a3;
    int x = tsum;
#pragma unroll
    for (int o = 1; o < 32; o <<= 1) {
        int y = __shfl_up_sync(0xffffffffu, x, o);
        if (lane >= o) x += y;
    }
    if (lane == 31) wsum[wid] = x;
    __syncthreads();
    int woff = 0;
    for (int w = 0; w < wid; w++) woff += wsum[w];
    int excl = g_BOFF[blockIdx.x] + woff + (x - tsum);
    if (base + 0 < NN) g_ROWPTR[base + 1] = excl + a0;
    if (base + 1 < NN) g_ROWPTR[base + 2] = excl + a0 + a1;
    if (base + 2 < NN) g_ROWPTR[base + 3] = excl + a0 + a1 + a2;
    if (base + 3 < NN) g_ROWPTR[base + 4] = excl + tsum;
    if (blockIdx.x == 0 && tid == 0) g_ROWPTR[0] = 0;
}

__global__ void scatter_kernel(const void* __restrict__ ei) {
    int e = blockIdx.x * blockDim.x + threadIdx.x;
    if (e >= EE) return;
    int is64 = g_EI64;
    int s = load_node(ei, (size_t)e, is64);
    int d = load_node(ei, (size_t)EE + e, is64);
    if ((unsigned)d >= NN || (unsigned)s >= NN) return;
    int pos = g_ROWPTR[d] + atomicAdd(&g_CUR[d], 1);
    if ((unsigned)pos < EE) g_SSRC[pos] = s;
}

// --------------------------------- GEMM1 --------------------------------------
__global__ void gemm1_kernel(const float* __restrict__ x, const float* __restrict__ W) {
    __shared__ float As[64][65];
    __shared__ float Bs[64][65];
    int tx = threadIdx.x & 15, ty = threadIdx.x >> 4;
    int rowBase = blockIdx.x * 64;
    int colBase = blockIdx.y * 64;
    float acc[4][4] = {};
    for (int kt = 0; kt < FIN; kt += 64) {
#pragma unroll
        for (int i = 0; i < 16; i++) {
            int idx = threadIdx.x + i * 256;
            int r = idx >> 6, c = idx & 63;
            int gr = rowBase + r;
            As[r][c] = (gr < NN) ? x[(size_t)gr * FIN + kt + c] : 0.0f;
        }
#pragma unroll
        for (int i = 0; i < 16; i++) {
            int idx = threadIdx.x + i * 256;
            int r = idx >> 6, c = idx & 63;
            int col = colBase + c;
            Bs[r][c] = W[(size_t)(col >> 5) * (FIN * HID) + (size_t)(kt + r) * HID + (col & 31)];
        }
        __syncthreads();
#pragma unroll 16
        for (int k = 0; k < 64; k++) {
            float a0 = As[ty * 4 + 0][k];
            float a1 = As[ty * 4 + 1][k];
            float a2 = As[ty * 4 + 2][k];
            float a3 = As[ty * 4 + 3][k];
            float b0 = Bs[k][tx * 4 + 0];
            float b1 = Bs[k][tx * 4 + 1];
            float b2 = Bs[k][tx * 4 + 2];
            float b3 = Bs[k][tx * 4 + 3];
            acc[0][0] += a0 * b0; acc[0][1] += a0 * b1; acc[0][2] += a0 * b2; acc[0][3] += a0 * b3;
            acc[1][0] += a1 * b0; acc[1][1] += a1 * b1; acc[1][2] += a1 * b2; acc[1][3] += a1 * b3;
            acc[2][0] += a2 * b0; acc[2][1] += a2 * b1; acc[2][2] += a2 * b2; acc[2][3] += a2 * b3;
            acc[3][0] += a3 * b0; acc[3][1] += a3 * b1; acc[3][2] += a3 * b2; acc[3][3] += a3 * b3;
        }
        __syncthreads();
    }
#pragma unroll
    for (int i = 0; i < 4; i++) {
        int gr = rowBase + ty * 4 + i;
        if (gr < NN) {
#pragma unroll
            for (int j = 0; j < 4; j++)
                g_H0[(size_t)gr * D1 + colBase + tx * 4 + j] = acc[i][j];
        }
    }
}

// --------------------------------- GEMM2 --------------------------------------
__global__ void gemm2_kernel(const float* __restrict__ Wout) {
    __shared__ float Bs[D1 * NCLS];
    int tid = threadIdx.x;
    for (int i = tid; i < D1 * NCLS; i += 256) Bs[i] = Wout[i];
    __syncthreads();
    int row = blockIdx.x * 256 + tid;
    if (row >= NN) return;
    const float* arow = g_H0 + (size_t)row * D1;
    float acc[NCLS] = {};
#pragma unroll 4
    for (int k = 0; k < D1; k++) {
        float a = __ldg(arow + k);
        const float* b = &Bs[k * NCLS];
#pragma unroll
        for (int c = 0; c < NCLS; c++) acc[c] += a * b[c];
    }
    float* orow = g_O0 + (size_t)row * NCLS;
#pragma unroll
    for (int c = 0; c < NCLS; c++) orow[c] = acc[c];
}

// --------------------- attention s,t for ALL 8 heads at once ------------------
__global__ void st8_kernel(const float* __restrict__ a_src,
                           const float* __restrict__ a_dst) {
    int gw = blockIdx.x * 8 + (threadIdx.x >> 5);
    int lane = threadIdx.x & 31;
    if (gw >= NN) return;
    const float* row = g_H0 + (size_t)gw * D1;
#pragma unroll
    for (int h = 0; h < HEADS; h++) {
        float v = row[h * HID + lane];
        float s = warp_sum(v * a_src[h * HID + lane]);
        float t = warp_sum(v * a_dst[h * HID + lane]);
        if (lane == 0) { g_S8[(size_t)gw * 8 + h] = s; g_T8[(size_t)gw * 8 + h] = t; }
    }
}

// ---------- 4-head fused attention weights (unnormalized) + per-dst inv -------
__global__ void attn4_kernel(int g) {
    int d = blockIdx.x * 8 + (threadIdx.x >> 5);
    int lane = threadIdx.x & 31;
    if (d >= NN) return;
    int start = g_ROWPTR[d], end = g_ROWPTR[d + 1];
    if (start == end) {
        if (lane == 0) *(float4*)&g_INV4[(size_t)d * 4] = make_float4(0.f, 0.f, 0.f, 0.f);
        return;
    }
    float4 t4 = *(const float4*)&g_T8[(size_t)d * 8 + g * 4];
    float m0 = -INFINITY, m1 = -INFINITY, m2 = -INFINITY, m3 = -INFINITY;
    for (int e = start + lane; e < end; e += 32) {
        int s = g_SSRC[e];
        float4 s4 = *(const float4*)&g_S8[(size_t)s * 8 + g * 4];
        float e0 = s4.x + t4.x; e0 = (e0 >= 0.f) ? e0 : LRA * e0;
        float e1 = s4.y + t4.y; e1 = (e1 >= 0.f) ? e1 : LRA * e1;
        float e2 = s4.z + t4.z; e2 = (e2 >= 0.f) ? e2 : LRA * e2;
        float e3 = s4.w + t4.w; e3 = (e3 >= 0.f) ? e3 : LRA * e3;
        m0 = fmaxf(m0, e0); m1 = fmaxf(m1, e1); m2 = fmaxf(m2, e2); m3 = fmaxf(m3, e3);
    }
    m0 = warp_max(m0); m1 = warp_max(m1); m2 = warp_max(m2); m3 = warp_max(m3);
    float u0 = 0.f, u1 = 0.f, u2 = 0.f, u3 = 0.f;
    for (int e = start + lane; e < end; e += 32) {
        int s = g_SSRC[e];
        float4 s4 = *(const float4*)&g_S8[(size_t)s * 8 + g * 4];
        float e0 = s4.x + t4.x; e0 = (e0 >= 0.f) ? e0 : LRA * e0;
        float e1 = s4.y + t4.y; e1 = (e1 >= 0.f) ? e1 : LRA * e1;
        float e2 = s4.z + t4.z; e2 = (e2 >= 0.f) ? e2 : LRA * e2;
        float e3 = s4.w + t4.w; e3 = (e3 >= 0.f) ? e3 : LRA * e3;
        float p0 = expf(e0 - m0), p1 = expf(e1 - m1);
        float p2 = expf(e2 - m2), p3 = expf(e3 - m3);
        *(float4*)&g_WBUF[(size_t)e * 4] = make_float4(p0, p1, p2, p3);
        u0 += p0; u1 += p1; u2 += p2; u3 += p3;
    }
    u0 = warp_sum(u0); u1 = warp_sum(u1); u2 = warp_sum(u2); u3 = warp_sum(u3);
    if (lane == 0) {
        float4 inv = make_float4(1.f / (u0 + 1e-16f), 1.f / (u1 + 1e-16f),
                                 1.f / (u2 + 1e-16f), 1.f / (u3 + 1e-16f));
        *(float4*)&g_INV4[(size_t)d * 4] = inv;
    }
}

// ------------------ 4-head fused diffusion hop (warp per dst) -----------------
// mode 0: gather H0 group slice -> FA.  mode 1: gather FA -> elu -> H0 in place.
__global__ void hop4_kernel(int g, int mode) {
    int d = blockIdx.x * 8 + (threadIdx.x >> 5);
    int lane = threadIdx.x & 31;
    if (d >= NN) return;
    int start = g_ROWPTR[d], end = g_ROWPTR[d + 1];
    float a0 = 0.f, a1 = 0.f, a2 = 0.f, a3 = 0.f;
    const float* srcbase;
    size_t stride, off;
    if (mode == 0) { srcbase = g_H0; stride = D1; off = (size_t)g * 128; }
    else           { srcbase = g_FA; stride = 128; off = 0; }

    int e = start;
    for (; e + 2 <= end; e += 2) {
        int s0 = g_SSRC[e], s1 = g_SSRC[e + 1];
        float4 w0 = *(const float4*)&g_WBUF[(size_t)e * 4];
        float4 w1 = *(const float4*)&g_WBUF[(size_t)(e + 1) * 4];
        const float* r0 = srcbase + (size_t)s0 * stride + off + lane;
        const float* r1 = srcbase + (size_t)s1 * stride + off + lane;
        float v00 = r0[0], v01 = r0[32], v02 = r0[64], v03 = r0[96];
        float v10 = r1[0], v11 = r1[32], v12 = r1[64], v13 = r1[96];
        a0 += w0.x * v00 + w1.x * v10;
        a1 += w0.y * v01 + w1.y * v11;
        a2 += w0.z * v02 + w1.z * v12;
        a3 += w0.w * v03 + w1.w * v13;
    }
    if (e < end) {
        int s0 = g_SSRC[e];
        float4 w0 = *(const float4*)&g_WBUF[(size_t)e * 4];
        const float* r0 = srcbase + (size_t)s0 * stride + off + lane;
        a0 += w0.x * r0[0];
        a1 += w0.y * r0[32];
        a2 += w0.z * r0[64];
        a3 += w0.w * r0[96];
    }
    float4 inv = *(const float4*)&g_INV4[(size_t)d * 4];
    float* h0r = g_H0 + (size_t)d * D1 + (size_t)g * 128 + lane;
    float v0 = ONE_MB * a0 * inv.x + BETA * h0r[0];
    float v1 = ONE_MB * a1 * inv.y + BETA * h0r[32];
    float v2 = ONE_MB * a2 * inv.z + BETA * h0r[64];
    float v3 = ONE_MB * a3 * inv.w + BETA * h0r[96];
    if (mode == 0) {
        float* fr = g_FA + (size_t)d * 128 + lane;
        fr[0] = v0; fr[32] = v1; fr[64] = v2; fr[96] = v3;
    } else {
        v0 = (v0 > 0.f) ? v0 : expm1f(v0);
        v1 = (v1 > 0.f) ? v1 : expm1f(v1);
        v2 = (v2 > 0.f) ? v2 : expm1f(v2);
        v3 = (v3 > 0.f) ? v3 : expm1f(v3);
        h0r[0] = v0; h0r[32] = v1; h0r[64] = v2; h0r[96] = v3;
    }
}

// ------------------------------ output layer -----------------------------------
__global__ void st40_kernel(const float* __restrict__ a_src,
                            const float* __restrict__ a_dst) {
    int gw = blockIdx.x * 8 + (threadIdx.x >> 5);
    int lane = threadIdx.x & 31;
    if (gw >= NN) return;
    const float* row = g_O0 + (size_t)gw * NCLS;
    float s = row[lane] * a_src[lane];
    float t = row[lane] * a_dst[lane];
    if (lane < 8) {
        s += row[32 + lane] * a_src[32 + lane];
        t += row[32 + lane] * a_dst[32 + lane];
    }
    s = warp_sum(s);
    t = warp_sum(t);
    if (lane == 0) { g_S[gw] = s; g_T[gw] = t; }
}

__global__ void attn_w_kernel() {      // normalized weights into g_WBUF[0..EE)
    int d = blockIdx.x * 8 + (threadIdx.x >> 5);
    int lane = threadIdx.x & 31;
    if (d >= NN) return;
    int start = g_ROWPTR[d], end = g_ROWPTR[d + 1];
    if (start == end) return;
    float td = g_T[d];
    float m = -INFINITY;
    for (int e = start + lane; e < end; e += 32) {
        float ev = g_S[g_SSRC[e]] + td;
        ev = (ev >= 0.f) ? ev : LRA * ev;
        m = fmaxf(m, ev);
    }
    m = warp_max(m);
    float sum = 0.f;
    for (int e = start + lane; e < end; e += 32) {
        float ev = g_S[g_SSRC[e]] + td;
        ev = (ev >= 0.f) ? ev : LRA * ev;
        float p = expf(ev - m);
        g_WBUF[e] = p;
        sum += p;
    }
    sum = warp_sum(sum);
    float inv = 1.f / (sum + 1e-16f);
    for (int e = start + lane; e < end; e += 32) g_WBUF[e] *= inv;
}

__global__ void hop40_kernel(int mode, float* __restrict__ out) {
    int d = blockIdx.x * 8 + (threadIdx.x >> 5);
    int lane = threadIdx.x & 31;
    if (d >= NN) return;
    int start = g_ROWPTR[d], end = g_ROWPTR[d + 1];
    float acca = 0.f, accb = 0.f;
    bool hi = (lane < 8);
    const float* base = (mode == 0) ? g_O0 : g_GA;
    for (int e = start; e < end; e++) {
        int s = g_SSRC[e];
        float w = g_WBUF[e];
        const float* row = base + (size_t)s * NCLS;
        acca += w * row[lane];
        if (hi) accb += w * row[32 + lane];
    }
    const float* h0row = g_O0 + (size_t)d * NCLS;
    float va = ONE_MB * acca + BETA * h0row[lane];
    float vb = hi ? (ONE_MB * accb + BETA * h0row[32 + lane]) : 0.f;
    if (mode == 0) {
        float* orow = g_GA + (size_t)d * NCLS;
        orow[lane] = va;
        if (hi) orow[32 + lane] = vb;
    } else {
        float ea = (va > 0.f) ? va : expm1f(va);
        float eb = hi ? ((vb > 0.f) ? vb : expm1f(vb)) : -INFINITY;
        float mx = warp_max(fmaxf(ea, eb));
        float se = expf(ea - mx) + (hi ? expf(eb - mx) : 0.f);
        se = warp_sum(se);
        float lse = mx + logf(se);
        float* orow = out + (size_t)d * NCLS;
        orow[lane] = ea - lse;
        if (hi) orow[32 + lane] = eb - lse;
    }
}

// --------------------------------- launch -------------------------------------
extern "C" void kernel_launch(void* const* d_in, const int* in_sizes, int n_in,
                              void* d_out, int out_size) {
    const float* x     = (const float*)d_in[0];
    const void*  ei    = d_in[1];
    const float* W     = (const float*)d_in[2];
    const float* a_src = (const float*)d_in[3];
    const float* a_dst = (const float*)d_in[4];
    const float* Wout  = (const float*)d_in[5];
    const float* a_so  = (const float*)d_in[6];
    const float* a_do  = (const float*)d_in[7];
    float*       out   = (float*)d_out;

    const int NWARP_GRID = (NN + 7) / 8;
    const int EGRID = (EE + 255) / 256;
    const int NGRID = (NN + 255) / 256;

    sniff_kernel<<<1, 256>>>((const int*)ei);
    zero_counts_kernel<<<NGRID, 256>>>();
    build_deg_kernel<<<EGRID, 256>>>(ei);
    scanA_kernel<<<NBLK, 256>>>();
    scanB_kernel<<<1, 128>>>();
    scanC_kernel<<<NBLK, 256>>>();
    scatter_kernel<<<EGRID, 256>>>(ei);

    gemm1_kernel<<<dim3((NN + 63) / 64, D1 / 64), 256>>>(x, W);
    st8_kernel<<<NWARP_GRID, 256>>>(a_src, a_dst);

    for (int g = 0; g < 2; g++) {
        attn4_kernel<<<NWARP_GRID, 256>>>(g);
        hop4_kernel<<<NWARP_GRID, 256>>>(g, 0);
        hop4_kernel<<<NWARP_GRID, 256>>>(g, 1);
    }

    gemm2_kernel<<<(NN + 255) / 256, 256>>>(Wout);

    st40_kernel<<<NWARP_GRID, 256>>>(a_so, a_do);
    attn_w_kernel<<<NWARP_GRID, 256>>>();
    hop40_kernel<<<NWARP_GRID, 256>>>(0, nullptr);
    hop40_kernel<<<NWARP_GRID, 256>>>(1, out);
}

// round 6
// speedup vs baseline: 1.4268x; 1.1396x over previous
#include <cuda_runtime.h>
#include <cuda_bf16.h>
#include <math.h>

#define NN 100000
#define EE 1600000
#define FIN 128
#define HID 32
#define HEADS 8
#define D1 256        // HEADS*HID
#define NCLS 40
#define BETA 0.1f
#define ONE_MB 0.9f   // 1-beta
#define LRA 0.2f      // leaky relu alpha
#define SCB 1024
#define NBLK ((NN + SCB - 1) / SCB)

// ------------- scratch (device globals; total ~237 MB, < 256 MB) -------------
__device__ __align__(128) float g_H0[(size_t)NN * D1];    // x@Wcat; layer-1 out in place
__device__ __align__(128) float g_FA[(size_t)NN * 128];   // hop-1 scratch; reused as GA
__device__ __align__(128) float g_O0[(size_t)NN * NCLS];  // H @ W_out
__device__ __align__(128) float g_WBUF[2][(size_t)EE * 4];// unnorm attn w, group-packed
__device__ __align__(128) int   g_SSRC[EE];               // src sorted by dst (CSR)
__device__ __align__(128) float g_S8[(size_t)NN * 8];
__device__ __align__(128) float g_T8[(size_t)NN * 8];
__device__ __align__(128) float g_INV8[(size_t)NN * 8];
__device__ int   g_ROWPTR[NN + 1];
__device__ int   g_DEG[NN];
__device__ int   g_CUR[NN];
__device__ int   g_BSUM[NBLK];
__device__ int   g_BOFF[NBLK];
__device__ int   g_EI64;

// ------------------------------- helpers --------------------------------------
__device__ __forceinline__ float warp_sum(float v) {
#pragma unroll
    for (int o = 16; o > 0; o >>= 1) v += __shfl_xor_sync(0xffffffffu, v, o);
    return v;
}
__device__ __forceinline__ float warp_max(float v) {
#pragma unroll
    for (int o = 16; o > 0; o >>= 1) v = fmaxf(v, __shfl_xor_sync(0xffffffffu, v, o));
    return v;
}
__device__ __forceinline__ int warp_sum_i(int v) {
#pragma unroll
    for (int o = 16; o > 0; o >>= 1) v += __shfl_xor_sync(0xffffffffu, v, o);
    return v;
}
__device__ __forceinline__ float sel4(float4 w, int h) {
    return (h == 0) ? w.x : (h == 1) ? w.y : (h == 2) ? w.z : w.w;
}

// ------------------------- edge dtype sniff (parallel) -------------------------
__global__ void sniff_kernel(const int* __restrict__ ei32) {
    int bad = 0;
    for (int i = threadIdx.x; i < 512; i += 256)
        bad |= (ei32[2 * i + 1] != 0);
    bad = __syncthreads_or(bad);
    if (threadIdx.x == 0) g_EI64 = bad ? 0 : 1;
}

__device__ __forceinline__ int load_node(const void* ei, size_t pos, int is64) {
    if (is64) return (int)((const long long*)ei)[pos];
    return ((const int*)ei)[pos];
}

// ------------------------------ CSR build -------------------------------------
__global__ void zero_counts_kernel() {
    int i = blockIdx.x * blockDim.x + threadIdx.x;
    if (i < NN) { g_DEG[i] = 0; g_CUR[i] = 0; }
}

__global__ void build_deg_kernel(const void* __restrict__ ei) {
    int e = blockIdx.x * blockDim.x + threadIdx.x;
    if (e >= EE) return;
    int d = load_node(ei, (size_t)EE + e, g_EI64);
    if ((unsigned)d < NN) atomicAdd(&g_DEG[d], 1);
}

__global__ void scanA_kernel() {
    __shared__ int wsum[8];
    int tid = threadIdx.x;
    int base = blockIdx.x * SCB + tid * 4;
    int s = 0;
#pragma unroll
    for (int j = 0; j < 4; j++) { int i = base + j; if (i < NN) s += g_DEG[i]; }
    s = warp_sum_i(s);
    if ((tid & 31) == 0) wsum[tid >> 5] = s;
    __syncthreads();
    if (tid == 0) {
        int t = 0;
#pragma unroll
        for (int w = 0; w < 8; w++) t += wsum[w];
        g_BSUM[blockIdx.x] = t;
    }
}

__global__ void scanB_kernel() {
    __shared__ int sm[4];
    int tid = threadIdx.x, lane = tid & 31, wid = tid >> 5;
    int v = (tid < NBLK) ? g_BSUM[tid] : 0;
    int x = v;
#pragma unroll
    for (int o = 1; o < 32; o <<= 1) {
        int y = __shfl_up_sync(0xffffffffu, x, o);
        if (lane >= o) x += y;
    }
    if (lane == 31) sm[wid] = x;
    __syncthreads();
    int woff = 0;
    for (int w = 0; w < wid; w++) woff += sm[w];
    if (tid < NBLK) g_BOFF[tid] = woff + x - v;
}

__global__ void scanC_kernel() {
    __shared__ int wsum[8];
    int tid = threadIdx.x, lane = tid & 31, wid = tid >> 5;
    int base = blockIdx.x * SCB + tid * 4;
    int a0 = (base + 0 < NN) ? g_DEG[base + 0] : 0;
    int a1 = (base + 1 < NN) ? g_DEG[base + 1] : 0;
    int a2 = (base + 2 < NN) ? g_DEG[base + 2] : 0;
    int a3 = (base + 3 < NN) ? g_DEG[base + 3] : 0;
    int tsum = a0 + a1 + a2 + a3;
    int x = tsum;
#pragma unroll
    for (int o = 1; o < 32; o <<= 1) {
        int y = __shfl_up_sync(0xffffffffu, x, o);
        if (lane >= o) x += y;
    }
    if (lane == 31) wsum[wid] = x;
    __syncthreads();
    int woff = 0;
    for (int w = 0; w < wid; w++) woff += wsum[w];
    int excl = g_BOFF[blockIdx.x] + woff + (x - tsum);
    if (base + 0 < NN) g_ROWPTR[base + 1] = excl + a0;
    if (base + 1 < NN) g_ROWPTR[base + 2] = excl + a0 + a1;
    if (base + 2 < NN) g_ROWPTR[base + 3] = excl + a0 + a1 + a2;
    if (base + 3 < NN) g_ROWPTR[base + 4] = excl + tsum;
    if (blockIdx.x == 0 && tid == 0) g_ROWPTR[0] = 0;
}

__global__ void scatter_kernel(const void* __restrict__ ei) {
    int e = blockIdx.x * blockDim.x + threadIdx.x;
    if (e >= EE) return;
    int is64 = g_EI64;
    int s = load_node(ei, (size_t)e, is64);
    int d = load_node(ei, (size_t)EE + e, is64);
    if ((unsigned)d >= NN || (unsigned)s >= NN) return;
    int pos = g_ROWPTR[d] + atomicAdd(&g_CUR[d], 1);
    if ((unsigned)pos < EE) g_SSRC[pos] = s;
}

// --------------------------------- GEMM1 --------------------------------------
// H0 = x[N,128] @ Wcat[128,256].  Block 128x64, 8x4 per thread, float4 smem.
__global__ void __launch_bounds__(256) gemm1_kernel(const float* __restrict__ x,
                                                    const float* __restrict__ W) {
    __shared__ float As[32][132];   // [k][m], padded (132*4 % 16 == 0)
    __shared__ float Bs[32][68];    // [k][n], padded (68*4 % 16 == 0)
    int tid = threadIdx.x;
    int tx = tid & 15;        // 4 cols each
    int ty = tid >> 4;        // 8 rows each
    int rowBase = blockIdx.x * 128;
    int colBase = blockIdx.y * 64;
    float acc[8][4] = {};
    for (int kt = 0; kt < FIN; kt += 32) {
#pragma unroll
        for (int p = 0; p < 4; p++) {
            int idx = tid + p * 256;          // 0..1023 float4 slots
            int r = idx & 127;
            int kq = idx >> 7;                // 0..7
            int gr = rowBase + r;
            float4 v = make_float4(0.f, 0.f, 0.f, 0.f);
            if (gr < NN) v = *(const float4*)&x[(size_t)gr * FIN + kt + kq * 4];
            As[kq * 4 + 0][r] = v.x;
            As[kq * 4 + 1][r] = v.y;
            As[kq * 4 + 2][r] = v.z;
            As[kq * 4 + 3][r] = v.w;
        }
#pragma unroll
        for (int p = 0; p < 8; p++) {
            int idx = tid + p * 256;
            int nn = idx & 63;
            int k = idx >> 6;
            int col = colBase + nn;
            Bs[k][nn] = W[(size_t)(col >> 5) * (FIN * HID) + (size_t)(kt + k) * HID + (col & 31)];
        }
        __syncthreads();
#pragma unroll
        for (int k = 0; k < 32; k++) {
            float4 a0 = *(const float4*)&As[k][ty * 8];
            float4 a1 = *(const float4*)&As[k][ty * 8 + 4];
            float4 b  = *(const float4*)&Bs[k][tx * 4];
            float am[8] = {a0.x, a0.y, a0.z, a0.w, a1.x, a1.y, a1.z, a1.w};
            float bn[4] = {b.x, b.y, b.z, b.w};
#pragma unroll
            for (int i = 0; i < 8; i++)
#pragma unroll
                for (int j = 0; j < 4; j++)
                    acc[i][j] += am[i] * bn[j];
        }
        __syncthreads();
    }
#pragma unroll
    for (int i = 0; i < 8; i++) {
        int gr = rowBase + ty * 8 + i;
        if (gr < NN)
            *(float4*)&g_H0[(size_t)gr * D1 + colBase + tx * 4] =
                make_float4(acc[i][0], acc[i][1], acc[i][2], acc[i][3]);
    }
}

// --------------------------------- GEMM2 --------------------------------------
__global__ void gemm2_kernel(const float* __restrict__ Wout) {
    __shared__ float Bs[D1 * NCLS];
    int tid = threadIdx.x;
    for (int i = tid; i < D1 * NCLS; i += 256) Bs[i] = Wout[i];
    __syncthreads();
    int row = blockIdx.x * 256 + tid;
    if (row >= NN) return;
    const float* arow = g_H0 + (size_t)row * D1;
    float acc[NCLS] = {};
#pragma unroll 4
    for (int k = 0; k < D1; k++) {
        float a = __ldg(arow + k);
        const float* b = &Bs[k * NCLS];
#pragma unroll
        for (int c = 0; c < NCLS; c++) acc[c] += a * b[c];
    }
    float* orow = g_O0 + (size_t)row * NCLS;
#pragma unroll
    for (int c = 0; c < NCLS; c++) orow[c] = acc[c];
}

// --------------------- attention s,t for ALL 8 heads at once ------------------
__global__ void st8_kernel(const float* __restrict__ a_src,
                           const float* __restrict__ a_dst) {
    int gw = blockIdx.x * 8 + (threadIdx.x >> 5);
    int lane = threadIdx.x & 31;
    if (gw >= NN) return;
    const float* row = g_H0 + (size_t)gw * D1;
#pragma unroll
    for (int h = 0; h < HEADS; h++) {
        float v = row[h * HID + lane];
        float s = warp_sum(v * a_src[h * HID + lane]);
        float t = warp_sum(v * a_dst[h * HID + lane]);
        if (lane == 0) { g_S8[(size_t)gw * 8 + h] = s; g_T8[(size_t)gw * 8 + h] = t; }
    }
}

// ------------ 8-head fused attention weights (unnormalized) + INV --------------
__global__ void attn8_kernel() {
    int d = blockIdx.x * 8 + (threadIdx.x >> 5);
    int lane = threadIdx.x & 31;
    if (d >= NN) return;
    int start = g_ROWPTR[d], end = g_ROWPTR[d + 1];
    if (start == end) {
        if (lane == 0) {
            float4 z = make_float4(0.f, 0.f, 0.f, 0.f);
            *(float4*)&g_INV8[(size_t)d * 8] = z;
            *(float4*)&g_INV8[(size_t)d * 8 + 4] = z;
        }
        return;
    }
    float4 ta = *(const float4*)&g_T8[(size_t)d * 8];
    float4 tb = *(const float4*)&g_T8[(size_t)d * 8 + 4];
    float t[8] = {ta.x, ta.y, ta.z, ta.w, tb.x, tb.y, tb.z, tb.w};
    float m[8];
#pragma unroll
    for (int i = 0; i < 8; i++) m[i] = -INFINITY;
    for (int e = start + lane; e < end; e += 32) {
        int s = g_SSRC[e];
        float4 sa = *(const float4*)&g_S8[(size_t)s * 8];
        float4 sb = *(const float4*)&g_S8[(size_t)s * 8 + 4];
        float sv[8] = {sa.x, sa.y, sa.z, sa.w, sb.x, sb.y, sb.z, sb.w};
#pragma unroll
        for (int i = 0; i < 8; i++) {
            float ev = sv[i] + t[i];
            ev = (ev >= 0.f) ? ev : LRA * ev;
            m[i] = fmaxf(m[i], ev);
        }
    }
#pragma unroll
    for (int i = 0; i < 8; i++) m[i] = warp_max(m[i]);
    float u[8] = {};
    for (int e = start + lane; e < end; e += 32) {
        int s = g_SSRC[e];
        float4 sa = *(const float4*)&g_S8[(size_t)s * 8];
        float4 sb = *(const float4*)&g_S8[(size_t)s * 8 + 4];
        float sv[8] = {sa.x, sa.y, sa.z, sa.w, sb.x, sb.y, sb.z, sb.w};
        float p[8];
#pragma unroll
        for (int i = 0; i < 8; i++) {
            float ev = sv[i] + t[i];
            ev = (ev >= 0.f) ? ev : LRA * ev;
            p[i] = expf(ev - m[i]);
            u[i] += p[i];
        }
        *(float4*)&g_WBUF[0][(size_t)e * 4] = make_float4(p[0], p[1], p[2], p[3]);
        *(float4*)&g_WBUF[1][(size_t)e * 4] = make_float4(p[4], p[5], p[6], p[7]);
    }
#pragma unroll
    for (int i = 0; i < 8; i++) u[i] = warp_sum(u[i]);
    if (lane == 0) {
        *(float4*)&g_INV8[(size_t)d * 8] =
            make_float4(1.f / (u[0] + 1e-16f), 1.f / (u[1] + 1e-16f),
                        1.f / (u[2] + 1e-16f), 1.f / (u[3] + 1e-16f));
        *(float4*)&g_INV8[(size_t)d * 8 + 4] =
            make_float4(1.f / (u[4] + 1e-16f), 1.f / (u[5] + 1e-16f),
                        1.f / (u[6] + 1e-16f), 1.f / (u[7] + 1e-16f));
    }
}

// ------------------ 4-head fused diffusion hop (warp per dst) -----------------
// lane covers 4 contiguous floats (cols lane*4..+3); head = lane>>3.
// mode 0: gather H0 group slice -> FA.  mode 1: gather FA -> elu -> H0 in place.
__global__ void hop4_kernel(int g, int mode) {
    int d = blockIdx.x * 8 + (threadIdx.x >> 5);
    int lane = threadIdx.x & 31;
    if (d >= NN) return;
    int h = lane >> 3;
    int start = g_ROWPTR[d], end = g_ROWPTR[d + 1];
    const float* wb = g_WBUF[g];
    float4 acc = make_float4(0.f, 0.f, 0.f, 0.f);
    int e = start;
    for (; e + 2 <= end; e += 2) {
        int s0 = g_SSRC[e], s1 = g_SSRC[e + 1];
        float4 w0 = *(const float4*)&wb[(size_t)e * 4];
        float4 w1 = *(const float4*)&wb[(size_t)(e + 1) * 4];
        const float4* r0;
        const float4* r1;
        if (mode == 0) {
            r0 = (const float4*)(g_H0 + (size_t)s0 * D1 + g * 128);
            r1 = (const float4*)(g_H0 + (size_t)s1 * D1 + g * 128);
        } else {
            r0 = (const float4*)(g_FA + (size_t)s0 * 128);
            r1 = (const float4*)(g_FA + (size_t)s1 * 128);
        }
        float4 v0 = r0[lane], v1 = r1[lane];
        float wv0 = sel4(w0, h), wv1 = sel4(w1, h);
        acc.x += wv0 * v0.x + wv1 * v1.x;
        acc.y += wv0 * v0.y + wv1 * v1.y;
        acc.z += wv0 * v0.z + wv1 * v1.z;
        acc.w += wv0 * v0.w + wv1 * v1.w;
    }
    if (e < end) {
        int s0 = g_SSRC[e];
        float4 w0 = *(const float4*)&wb[(size_t)e * 4];
        const float4* r0 = (mode == 0)
            ? (const float4*)(g_H0 + (size_t)s0 * D1 + g * 128)
            : (const float4*)(g_FA + (size_t)s0 * 128);
        float4 v0 = r0[lane];
        float wv0 = sel4(w0, h);
        acc.x += wv0 * v0.x; acc.y += wv0 * v0.y;
        acc.z += wv0 * v0.z; acc.w += wv0 * v0.w;
    }
    float4 inv4 = *(const float4*)&g_INV8[(size_t)d * 8 + g * 4];
    float invv = sel4(inv4, h);
    const float4* h0r = (const float4*)(g_H0 + (size_t)d * D1 + g * 128);
    float4 h0v = h0r[lane];
    float4 v;
    v.x = ONE_MB * acc.x * invv + BETA * h0v.x;
    v.y = ONE_MB * acc.y * invv + BETA * h0v.y;
    v.z = ONE_MB * acc.z * invv + BETA * h0v.z;
    v.w = ONE_MB * acc.w * invv + BETA * h0v.w;
    if (mode == 0) {
        ((float4*)(g_FA + (size_t)d * 128))[lane] = v;
    } else {
        v.x = (v.x > 0.f) ? v.x : expm1f(v.x);
        v.y = (v.y > 0.f) ? v.y : expm1f(v.y);
        v.z = (v.z > 0.f) ? v.z : expm1f(v.z);
        v.w = (v.w > 0.f) ? v.w : expm1f(v.w);
        ((float4*)(g_H0 + (size_t)d * D1 + g * 128))[lane] = v;
    }
}

// ------------------------------ output layer -----------------------------------
__global__ void st40_kernel(const float* __restrict__ a_src,
                            const float* __restrict__ a_dst) {
    int gw = blockIdx.x * 8 + (threadIdx.x >> 5);
    int lane = threadIdx.x & 31;
    if (gw >= NN) return;
    const float* row = g_O0 + (size_t)gw * NCLS;
    float s = row[lane] * a_src[lane];
    float t = row[lane] * a_dst[lane];
    if (lane < 8) {
        s += row[32 + lane] * a_src[32 + lane];
        t += row[32 + lane] * a_dst[32 + lane];
    }
    s = warp_sum(s);
    t = warp_sum(t);
    if (lane == 0) { g_S8[gw] = s; g_T8[gw] = t; }   // reuse S8/T8 (stride-1 phase)
}

__global__ void attn_w_kernel() {      // normalized weights into g_WBUF[0]
    int d = blockIdx.x * 8 + (threadIdx.x >> 5);
    int lane = threadIdx.x & 31;
    if (d >= NN) return;
    int start = g_ROWPTR[d], end = g_ROWPTR[d + 1];
    if (start == end) return;
    float* wb = g_WBUF[0];
    float td = g_T8[d];
    float m = -INFINITY;
    for (int e = start + lane; e < end; e += 32) {
        float ev = g_S8[g_SSRC[e]] + td;
        ev = (ev >= 0.f) ? ev : LRA * ev;
        m = fmaxf(m, ev);
    }
    m = warp_max(m);
    float sum = 0.f;
    for (int e = start + lane; e < end; e += 32) {
        float ev = g_S8[g_SSRC[e]] + td;
        ev = (ev >= 0.f) ? ev : LRA * ev;
        float p = expf(ev - m);
        wb[e] = p;
        sum += p;
    }
    sum = warp_sum(sum);
    float inv = 1.f / (sum + 1e-16f);
    for (int e = start + lane; e < end; e += 32) wb[e] *= inv;
}

__global__ void hop40_kernel(int mode, float* __restrict__ out) {
    int d = blockIdx.x * 8 + (threadIdx.x >> 5);
    int lane = threadIdx.x & 31;
    if (d >= NN) return;
    int start = g_ROWPTR[d], end = g_ROWPTR[d + 1];
    float acca = 0.f, accb = 0.f;
    bool hi = (lane < 8);
    const float* base = (mode == 0) ? g_O0 : g_FA;   // g_FA doubles as GA
    const float* wb = g_WBUF[0];
    for (int e = start; e < end; e++) {
        int s = g_SSRC[e];
        float w = wb[e];
        const float* row = base + (size_t)s * NCLS;
        acca += w * row[lane];
        if (hi) accb += w * row[32 + lane];
    }
    const float* h0row = g_O0 + (size_t)d * NCLS;
    float va = ONE_MB * acca + BETA * h0row[lane];
    float vb = hi ? (ONE_MB * accb + BETA * h0row[32 + lane]) : 0.f;
    if (mode == 0) {
        float* orow = g_FA + (size_t)d * NCLS;
        orow[lane] = va;
        if (hi) orow[32 + lane] = vb;
    } else {
        float ea = (va > 0.f) ? va : expm1f(va);
        float eb = hi ? ((vb > 0.f) ? vb : expm1f(vb)) : -INFINITY;
        float mx = warp_max(fmaxf(ea, eb));
        float se = expf(ea - mx) + (hi ? expf(eb - mx) : 0.f);
        se = warp_sum(se);
        float lse = mx + logf(se);
        float* orow = out + (size_t)d * NCLS;
        orow[lane] = ea - lse;
        if (hi) orow[32 + lane] = eb - lse;
    }
}

// --------------------------------- launch -------------------------------------
extern "C" void kernel_launch(void* const* d_in, const int* in_sizes, int n_in,
                              void* d_out, int out_size) {
    const float* x     = (const float*)d_in[0];
    const void*  ei    = d_in[1];
    const float* W     = (const float*)d_in[2];
    const float* a_src = (const float*)d_in[3];
    const float* a_dst = (const float*)d_in[4];
    const float* Wout  = (const float*)d_in[5];
    const float* a_so  = (const float*)d_in[6];
    const float* a_do  = (const float*)d_in[7];
    float*       out   = (float*)d_out;

    const int NWARP_GRID = (NN + 7) / 8;
    const int EGRID = (EE + 255) / 256;
    const int NGRID = (NN + 255) / 256;

    sniff_kernel<<<1, 256>>>((const int*)ei);
    zero_counts_kernel<<<NGRID, 256>>>();
    build_deg_kernel<<<EGRID, 256>>>(ei);
    scanA_kernel<<<NBLK, 256>>>();
    scanB_kernel<<<1, 128>>>();
    scanC_kernel<<<NBLK, 256>>>();
    scatter_kernel<<<EGRID, 256>>>(ei);

    gemm1_kernel<<<dim3((NN + 127) / 128, D1 / 64), 256>>>(x, W);
    st8_kernel<<<NWARP_GRID, 256>>>(a_src, a_dst);
    attn8_kernel<<<NWARP_GRID, 256>>>();

    for (int g = 0; g < 2; g++) {
        hop4_kernel<<<NWARP_GRID, 256>>>(g, 0);
        hop4_kernel<<<NWARP_GRID, 256>>>(g, 1);
    }

    gemm2_kernel<<<(NN + 255) / 256, 256>>>(Wout);

    st40_kernel<<<NWARP_GRID, 256>>>(a_so, a_do);
    attn_w_kernel<<<NWARP_GRID, 256>>>();
    hop40_kernel<<<NWARP_GRID, 256>>>(0, nullptr);
    hop40_kernel<<<NWARP_GRID, 256>>>(1, out);
}